// round 1
// baseline (speedup 1.0000x reference)
#include <cuda_runtime.h>
#include <cuda_bf16.h>
#include <math.h>

// ---------------- problem constants ----------------
#define L       2048
#define BATCH   2
#define DM      768
#define DI      1536          // d_inner
#define DS      128           // d_state
#define HD      64            // headdim
#define NH      24            // heads
#define CONVD   1792          // conv_dim = DI + 2*DS
#define NPROJ   3352          // 2*DI + 2*DS + NH
#define M4      4096          // BATCH * L tokens per direction

// ---------------- scratch (static device memory; no allocations) ----------------
__device__ float g_zx [2u * M4 * NPROJ];   // in_proj outputs, per direction (stored in scan order)
__device__ float g_xBC[2u * M4 * CONVD];   // conv+silu output
__device__ float g_dt [2u * M4 * NH];
__device__ float g_dA [2u * M4 * NH];
__device__ float g_y  [2u * M4 * DI];      // scan output -> gated/normed in place

// =====================================================================
// Kernel 1: in_proj GEMM  (per direction; direction 1 reads flipped x)
//   C[dir][m][n] = sum_k x_eff[m][k] * w[dir][n][k]
//   M=4096, N=3352, K=768.  BM=BN=128, BK=8, 256 threads, 8x8 per thread.
// =====================================================================
__global__ void __launch_bounds__(256) inproj_gemm(const float* __restrict__ x,
                                                   const float* __restrict__ w)
{
    const int dir = blockIdx.z;
    const int n0  = blockIdx.x * 128;
    const int m0  = blockIdx.y * 128;

    __shared__ float As[8][128];
    __shared__ float Bs[8][128];

    const int tid  = threadIdx.x;
    const int lrow = tid >> 1;          // 0..127
    const int lcol = (tid & 1) * 4;     // 0 or 4
    const int ty   = tid >> 4;          // 0..15
    const int tx   = tid & 15;          // 0..15

    // A source row (flip t for backward direction)
    const int m  = m0 + lrow;
    const int t  = m & (L - 1);
    const int st = dir ? (L - 1 - t) : t;
    const float* aptr = x + ((size_t)((m >> 11) * L + st)) * DM + lcol;

    const int n = n0 + lrow;
    const bool bval = (n < NPROJ);
    const float* bptr = w + (size_t)dir * NPROJ * DM + (size_t)n * DM + lcol;

    float acc[8][8];
#pragma unroll
    for (int i = 0; i < 8; ++i)
#pragma unroll
        for (int j = 0; j < 8; ++j) acc[i][j] = 0.f;

    for (int k0 = 0; k0 < DM; k0 += 8) {
        float4 av = *(const float4*)(aptr + k0);
        float4 bv = bval ? *(const float4*)(bptr + k0) : make_float4(0.f, 0.f, 0.f, 0.f);
        __syncthreads();
        As[lcol + 0][lrow] = av.x; As[lcol + 1][lrow] = av.y;
        As[lcol + 2][lrow] = av.z; As[lcol + 3][lrow] = av.w;
        Bs[lcol + 0][lrow] = bv.x; Bs[lcol + 1][lrow] = bv.y;
        Bs[lcol + 2][lrow] = bv.z; Bs[lcol + 3][lrow] = bv.w;
        __syncthreads();
#pragma unroll
        for (int k = 0; k < 8; ++k) {
            float a[8], bb[8];
            *(float4*)(a)      = *(const float4*)(&As[k][ty * 8]);
            *(float4*)(a + 4)  = *(const float4*)(&As[k][ty * 8 + 4]);
            *(float4*)(bb)     = *(const float4*)(&Bs[k][tx * 8]);
            *(float4*)(bb + 4) = *(const float4*)(&Bs[k][tx * 8 + 4]);
#pragma unroll
            for (int i = 0; i < 8; ++i)
#pragma unroll
                for (int j = 0; j < 8; ++j)
                    acc[i][j] = fmaf(a[i], bb[j], acc[i][j]);
        }
    }

#pragma unroll
    for (int i = 0; i < 8; ++i) {
        const int mm = m0 + ty * 8 + i;
        float* op = g_zx + ((size_t)(dir * M4 + mm)) * NPROJ;
#pragma unroll
        for (int j = 0; j < 8; ++j) {
            const int nn = n0 + tx * 8 + j;
            if (nn < NPROJ) op[nn] = acc[i][j];
        }
    }
}

// =====================================================================
// Kernel 2: dt = softplus(raw + dt_bias),  dA = exp(dt * (-exp(A_log)))
// =====================================================================
__global__ void dtdA_kernel(const float* __restrict__ dt_bias,
                            const float* __restrict__ A_log)
{
    const int idx = blockIdx.x * 256 + threadIdx.x;
    if (idx >= 2 * M4 * NH) return;
    const int hh  = idx % NH;
    const int rm  = idx / NH;           // dir*M4 + m
    const int dir = rm >> 12;
    const float raw = g_zx[(size_t)rm * NPROJ + (DI + CONVD) + hh] + dt_bias[dir * NH + hh];
    const float dtv = (raw > 20.f) ? raw : log1pf(expf(raw));
    const float A   = -expf(A_log[dir * NH + hh]);
    g_dt[idx] = dtv;
    g_dA[idx] = expf(dtv * A);
}

// =====================================================================
// Kernel 3: depthwise causal conv(4) + SiLU over the xBC channels
//   grid: (1, 64 t-chunks of 32, dir*2+b), 256 threads over channels
// =====================================================================
__global__ void __launch_bounds__(256) conv_kernel(const float* __restrict__ conv_w,
                                                   const float* __restrict__ conv_b)
{
    const int db  = blockIdx.z;            // dir*2 + b
    const int dir = db >> 1;
    const int b   = db & 1;
    const int t0  = blockIdx.y * 32;
    const int tid = threadIdx.x;

    __shared__ float s[35][256];

    for (int cb = 0; cb < CONVD; cb += 256) {
        const int c = cb + tid;
        __syncthreads();   // protect smem from previous chunk
#pragma unroll
        for (int r = 0; r < 35; ++r) {
            const int tin = t0 - 3 + r;
            float val = 0.f;
            if (tin >= 0)
                val = g_zx[((size_t)(dir * M4 + b * L + tin)) * NPROJ + DI + c];
            s[r][tid] = val;
        }
        __syncthreads();
        const float w0 = conv_w[(dir * CONVD + c) * 4 + 0];
        const float w1 = conv_w[(dir * CONVD + c) * 4 + 1];
        const float w2 = conv_w[(dir * CONVD + c) * 4 + 2];
        const float w3 = conv_w[(dir * CONVD + c) * 4 + 3];
        const float bias = conv_b[dir * CONVD + c];
#pragma unroll 4
        for (int tt = 0; tt < 32; ++tt) {
            float v = bias;
            v = fmaf(s[tt + 0][tid], w0, v);
            v = fmaf(s[tt + 1][tid], w1, v);
            v = fmaf(s[tt + 2][tid], w2, v);
            v = fmaf(s[tt + 3][tid], w3, v);
            const float o = v / (1.f + expf(-v));   // silu
            g_xBC[((size_t)(dir * M4 + b * L + t0 + tt)) * CONVD + c] = o;
        }
    }
}

// =====================================================================
// Kernel 4: selective scan.  One block per (head, batch, dir) = 96 blocks.
//   128 threads, each owns a 4(p) x 16(n) tile of the 64x128 state in regs.
//   Triple-buffered smem prefetch of per-step x/B/C/dt/dA (1 bar/step).
// =====================================================================
__global__ void __launch_bounds__(128) scan_kernel(const float* __restrict__ Dvec)
{
    const int h   = blockIdx.x;
    const int b   = blockIdx.y;
    const int dir = blockIdx.z;
    const int tid = threadIdx.x;
    const int ni  = tid & 7;      // 0..7  -> n = ni*16 + nn
    const int pi  = tid >> 3;     // 0..15 -> p = pi*4 + pp

    __shared__ float sx[3][64];
    __shared__ float sB[3][128];
    __shared__ float sC[3][128];
    __shared__ float ss[3][2];    // dt, dA

    const float Dval   = Dvec[dir * NH + h];
    const int rowbase  = dir * M4 + b * L;

    float hreg[4][16];
#pragma unroll
    for (int pp = 0; pp < 4; ++pp)
#pragma unroll
        for (int nn = 0; nn < 16; ++nn) hreg[pp][nn] = 0.f;

    // prologue: load step 0 into buffer 0
    {
        const float* row = g_xBC + (size_t)rowbase * CONVD;
        if (tid < 64) sx[0][tid] = row[h * HD + tid];
        sB[0][tid] = row[DI + tid];
        sC[0][tid] = row[DI + DS + tid];
        if (tid == 0) {
            ss[0][0] = g_dt[rowbase * NH + h];
            ss[0][1] = g_dA[rowbase * NH + h];
        }
    }
    __syncthreads();

    int cur = 0;
    for (int t = 0; t < L; ++t) {
        // prefetch t+1 into registers (latency hidden under compute)
        float rx = 0.f, rb = 0.f, rc = 0.f, rdt = 0.f, rdA = 0.f;
        if (t + 1 < L) {
            const float* row = g_xBC + (size_t)(rowbase + t + 1) * CONVD;
            if (tid < 64) rx = row[h * HD + tid];
            rb = row[DI + tid];
            rc = row[DI + DS + tid];
            if (tid == 0) {
                rdt = g_dt[(rowbase + t + 1) * NH + h];
                rdA = g_dA[(rowbase + t + 1) * NH + h];
            }
        }

        const float dt = ss[cur][0];
        const float dA = ss[cur][1];
        float xv[4], coef[4], acc[4];
#pragma unroll
        for (int pp = 0; pp < 4; ++pp) {
            xv[pp]   = sx[cur][pi * 4 + pp];
            coef[pp] = dt * xv[pp];
            acc[pp]  = 0.f;
        }
#pragma unroll
        for (int nn = 0; nn < 16; ++nn) {
            const float Bv = sB[cur][ni * 16 + nn];
            const float Cv = sC[cur][ni * 16 + nn];
#pragma unroll
            for (int pp = 0; pp < 4; ++pp) {
                const float hv = fmaf(hreg[pp][nn], dA, coef[pp] * Bv);
                hreg[pp][nn] = hv;
                acc[pp] = fmaf(hv, Cv, acc[pp]);
            }
        }
        // reduce partial y over the 8 n-lanes (low 3 bits of tid)
#pragma unroll
        for (int pp = 0; pp < 4; ++pp) {
            acc[pp] += __shfl_xor_sync(0xffffffffu, acc[pp], 1);
            acc[pp] += __shfl_xor_sync(0xffffffffu, acc[pp], 2);
            acc[pp] += __shfl_xor_sync(0xffffffffu, acc[pp], 4);
        }
        if (ni == 0) {
            float* yp = g_y + (size_t)(rowbase + t) * DI + h * HD + pi * 4;
#pragma unroll
            for (int pp = 0; pp < 4; ++pp)
                yp[pp] = fmaf(Dval, xv[pp], acc[pp]);
        }

        const int nxt = (cur == 2) ? 0 : cur + 1;
        if (t + 1 < L) {
            if (tid < 64) sx[nxt][tid] = rx;
            sB[nxt][tid] = rb;
            sC[nxt][tid] = rc;
            if (tid == 0) { ss[nxt][0] = rdt; ss[nxt][1] = rdA; }
        }
        __syncthreads();
        cur = nxt;
    }
}

// =====================================================================
// Kernel 5: y = y * silu(z);  y = y * rsqrt(mean(y^2)+eps) * norm_w  (in place)
// =====================================================================
__global__ void __launch_bounds__(256) gatenorm_kernel(const float* __restrict__ norm_w)
{
    const int row = blockIdx.x;          // dir*M4 + m
    const int dir = row >> 12;
    const int tid = threadIdx.x;
    float* yrow = g_y + (size_t)row * DI;
    const float* zrow = g_zx + (size_t)row * NPROJ;

    float v[6];
    float ssum = 0.f;
#pragma unroll
    for (int i = 0; i < 6; ++i) {
        const int c = tid + i * 256;
        const float zv = zrow[c];
        const float val = yrow[c] * (zv / (1.f + expf(-zv)));
        v[i] = val;
        ssum += val * val;
    }
#pragma unroll
    for (int o = 16; o > 0; o >>= 1)
        ssum += __shfl_xor_sync(0xffffffffu, ssum, o);

    __shared__ float red[8];
    if ((tid & 31) == 0) red[tid >> 5] = ssum;
    __syncthreads();
    if (tid == 0) {
        float tot = 0.f;
#pragma unroll
        for (int i = 0; i < 8; ++i) tot += red[i];
        red[0] = rsqrtf(tot / (float)DI + 1e-5f);
    }
    __syncthreads();
    const float scale = red[0];
#pragma unroll
    for (int i = 0; i < 6; ++i) {
        const int c = tid + i * 256;
        yrow[c] = v[i] * scale * norm_w[dir * DI + c];
    }
}

// =====================================================================
// Kernel 6: out_proj GEMM + bidirectional combine (flip dir=1 output)
//   out[m][n] = sum_d  y[d][m_d][:] . out_w[d][n][:]
//   M=4096, N=768, K=1536.  No edge guards needed.
// =====================================================================
__global__ void __launch_bounds__(256) outproj_gemm(const float* __restrict__ ow,
                                                    float* __restrict__ out)
{
    const int n0 = blockIdx.x * 128;   // 0..5
    const int m0 = blockIdx.y * 128;   // 0..31

    __shared__ float As[8][128];
    __shared__ float Bs[8][128];

    const int tid  = threadIdx.x;
    const int lrow = tid >> 1;
    const int lcol = (tid & 1) * 4;
    const int ty   = tid >> 4;
    const int tx   = tid & 15;

    float acc[8][8];
#pragma unroll
    for (int i = 0; i < 8; ++i)
#pragma unroll
        for (int j = 0; j < 8; ++j) acc[i][j] = 0.f;

    for (int d = 0; d < 2; ++d) {
        const int m = m0 + lrow;
        const int t = m & (L - 1);
        const int srcm = d ? (m - t + (L - 1 - t)) : m;
        const float* aptr = g_y + ((size_t)(d * M4 + srcm)) * DI + lcol;
        const float* bptr = ow + (size_t)d * DM * DI + (size_t)(n0 + lrow) * DI + lcol;

        for (int k0 = 0; k0 < DI; k0 += 8) {
            float4 av = *(const float4*)(aptr + k0);
            float4 bv = *(const float4*)(bptr + k0);
            __syncthreads();
            As[lcol + 0][lrow] = av.x; As[lcol + 1][lrow] = av.y;
            As[lcol + 2][lrow] = av.z; As[lcol + 3][lrow] = av.w;
            Bs[lcol + 0][lrow] = bv.x; Bs[lcol + 1][lrow] = bv.y;
            Bs[lcol + 2][lrow] = bv.z; Bs[lcol + 3][lrow] = bv.w;
            __syncthreads();
#pragma unroll
            for (int k = 0; k < 8; ++k) {
                float a[8], bb[8];
                *(float4*)(a)      = *(const float4*)(&As[k][ty * 8]);
                *(float4*)(a + 4)  = *(const float4*)(&As[k][ty * 8 + 4]);
                *(float4*)(bb)     = *(const float4*)(&Bs[k][tx * 8]);
                *(float4*)(bb + 4) = *(const float4*)(&Bs[k][tx * 8 + 4]);
#pragma unroll
                for (int i = 0; i < 8; ++i)
#pragma unroll
                    for (int j = 0; j < 8; ++j)
                        acc[i][j] = fmaf(a[i], bb[j], acc[i][j]);
            }
        }
    }

#pragma unroll
    for (int i = 0; i < 8; ++i) {
        const int mm = m0 + ty * 8 + i;
        float* op = out + (size_t)mm * DM + n0 + tx * 8;
#pragma unroll
        for (int j = 0; j < 8; ++j) op[j] = acc[i][j];
    }
}

// =====================================================================
// launch
// =====================================================================
extern "C" void kernel_launch(void* const* d_in, const int* in_sizes, int n_in,
                              void* d_out, int out_size)
{
    (void)in_sizes; (void)n_in; (void)out_size;
    const float* x       = (const float*)d_in[0];
    const float* in_w    = (const float*)d_in[1];
    const float* conv_w  = (const float*)d_in[2];
    const float* conv_b  = (const float*)d_in[3];
    const float* dt_bias = (const float*)d_in[4];
    const float* A_log   = (const float*)d_in[5];
    const float* Dp      = (const float*)d_in[6];
    const float* norm_w  = (const float*)d_in[7];
    const float* out_w   = (const float*)d_in[8];
    float* out = (float*)d_out;

    inproj_gemm<<<dim3((NPROJ + 127) / 128, M4 / 128, 2), 256>>>(x, in_w);
    dtdA_kernel<<<(2 * M4 * NH + 255) / 256, 256>>>(dt_bias, A_log);
    conv_kernel<<<dim3(1, L / 32, 4), 256>>>(conv_w, conv_b);
    scan_kernel<<<dim3(NH, BATCH, 2), 128>>>(Dp);
    gatenorm_kernel<<<2 * M4, 256>>>(norm_w);
    outproj_gemm<<<dim3(DM / 128, M4 / 128), 256>>>(out_w, out);
}

// round 3
// speedup vs baseline: 1.3706x; 1.3706x over previous
#include <cuda_runtime.h>
#include <cuda_bf16.h>
#include <math.h>
#include <cstdint>
#include <cstring>

// ---------------- problem constants ----------------
#define L       2048
#define BATCH   2
#define DM      768
#define DI      1536          // d_inner
#define DS      128           // d_state
#define HD      64            // headdim
#define NH      24            // heads
#define CONVD   1792          // conv_dim = DI + 2*DS
#define NPROJ   3352          // 2*DI + 2*DS + NH
#define M4      4096          // BATCH * L tokens per direction

// ---------------- scratch ----------------
__device__ float g_zx [2u * M4 * NPROJ];
__device__ float g_xBC[2u * M4 * CONVD];
__device__ float g_dt [2u * M4 * NH];
__device__ float g_dA [2u * M4 * NH];
__device__ float g_y  [2u * M4 * DI];

// =====================================================================
// helpers
// =====================================================================
__device__ __forceinline__ uint32_t smem_u32(const void* p) {
    uint32_t a;
    asm("{ .reg .u64 t; cvta.to.shared.u64 t, %1; cvt.u32.u64 %0, t; }" : "=r"(a) : "l"(p));
    return a;
}
__device__ __forceinline__ uint32_t b2u(__nv_bfloat162 v) {
    uint32_t u; memcpy(&u, &v, 4); return u;
}
__device__ __forceinline__ void ldsm4(uint32_t& r0, uint32_t& r1, uint32_t& r2, uint32_t& r3,
                                      uint32_t addr) {
    asm volatile("ldmatrix.sync.aligned.m8n8.x4.shared.b16 {%0,%1,%2,%3}, [%4];"
        : "=r"(r0), "=r"(r1), "=r"(r2), "=r"(r3) : "r"(addr));
}
__device__ __forceinline__ void mma16816(float* c, const uint32_t* a, const uint32_t* b) {
    asm volatile(
        "mma.sync.aligned.m16n8k16.row.col.f32.bf16.bf16.f32 "
        "{%0,%1,%2,%3}, {%4,%5,%6,%7}, {%8,%9}, {%0,%1,%2,%3};"
        : "+f"(c[0]), "+f"(c[1]), "+f"(c[2]), "+f"(c[3])
        : "r"(a[0]), "r"(a[1]), "r"(a[2]), "r"(a[3]), "r"(b[0]), "r"(b[1]));
}
// split a float4 into bf16 hi / lo pairs (packed)
__device__ __forceinline__ void split4(float4 v, uint2& h, uint2& l) {
    __nv_bfloat162 h0 = __float22bfloat162_rn(make_float2(v.x, v.y));
    __nv_bfloat162 h1 = __float22bfloat162_rn(make_float2(v.z, v.w));
    float2 f0 = __bfloat1622float2(h0), f1 = __bfloat1622float2(h1);
    __nv_bfloat162 l0 = __float22bfloat162_rn(make_float2(v.x - f0.x, v.y - f0.y));
    __nv_bfloat162 l1 = __float22bfloat162_rn(make_float2(v.z - f1.x, v.w - f1.y));
    h = make_uint2(b2u(h0), b2u(h1));
    l = make_uint2(b2u(l0), b2u(l1));
}

// =====================================================================
// split-bf16 GEMM on the HMMA pipe (mma.sync m16n8k16, 3 products).
//   C[m][n] = sum_k A[m][k] * B[n][k]   (fp32-accurate via hi/lo split)
//   MODE 0: in_proj  A=x (flipped for dir=blockIdx.z), B=in_w[dir] -> g_zx
//           M=4096, N=3352 (guarded), K=768
//   MODE 1: out_proj A=g_y(dir0) + g_y(dir1 flipped), B=out_w[d]  -> out
//           M=4096, N=768, K=2x1536 (accumulated over dirs)
// Block tile 128x128x32, 8 warps (2x4), warp tile 64x32.
// =====================================================================
#define SSTR 40   // smem row stride in bf16 elems (80 bytes, conflict-free)

template <int MODE>
__global__ void __launch_bounds__(256) mma_gemm(const float* __restrict__ Ag,
                                                const float* __restrict__ Bg,
                                                float* __restrict__ Cg)
{
    __shared__ __nv_bfloat16 sAh[128 * SSTR], sAl[128 * SSTR];
    __shared__ __nv_bfloat16 sBh[128 * SSTR], sBl[128 * SSTR];

    const int tid  = threadIdx.x;
    const int wid  = tid >> 5;
    const int lane = tid & 31;
    const int n0   = blockIdx.x * 128;
    const int m0   = blockIdx.y * 128;
    const int dir0 = blockIdx.z;

    // ---- loader mapping: 2 threads per row, 16 floats each ----
    const int r  = tid >> 1;
    const int ch = (tid & 1) * 16;

    const float* arowbase = nullptr;
    if (MODE == 0) {
        const int m = m0 + r, t = m & (L - 1);
        const int st = dir0 ? (L - 1 - t) : t;
        arowbase = Ag + ((size_t)((m >> 11) * L + st)) * DM;
    }
    const int  nrow   = n0 + r;
    const bool bvalid = (MODE == 0) ? (nrow < NPROJ) : true;

    const int S = (MODE == 0) ? (DM / 32) : (2 * (DI / 32));  // 24 or 96

    float4 pa[4], pb[4];

    // ---- prologue: load slab 0 ----
    {
        const float* ap;
        const float* bp;
        if (MODE == 0) {
            ap = arowbase + ch;
            bp = Bg + (size_t)dir0 * NPROJ * DM + (size_t)nrow * DM + ch;
        } else {
            const int m = m0 + r;
            ap = g_y + (size_t)m * DI + ch;        // d=0, k0=0
            bp = Bg + (size_t)nrow * DI + ch;
        }
#pragma unroll
        for (int q = 0; q < 4; ++q) pa[q] = *(const float4*)(ap + q * 4);
        if (bvalid) {
#pragma unroll
            for (int q = 0; q < 4; ++q) pb[q] = *(const float4*)(bp + q * 4);
        } else {
#pragma unroll
            for (int q = 0; q < 4; ++q) pb[q] = make_float4(0.f, 0.f, 0.f, 0.f);
        }
    }

    float acc[4][4][4];
#pragma unroll
    for (int i = 0; i < 4; ++i)
#pragma unroll
        for (int j = 0; j < 4; ++j)
#pragma unroll
            for (int k = 0; k < 4; ++k) acc[i][j][k] = 0.f;

    const uint32_t uAh = smem_u32(sAh), uAl = smem_u32(sAl);
    const uint32_t uBh = smem_u32(sBh), uBl = smem_u32(sBl);

    const int wm  = (wid >> 2) * 64;
    const int wn  = (wid & 3) * 32;
    const int arl = (lane & 7) + ((lane >> 3) & 1) * 8;   // A ldmatrix row
    const int akb = (lane >> 4) * 16;                     // A ldmatrix k-byte
    const int brl = (lane & 7) + (lane >> 4) * 8;         // B ldmatrix row
    const int bkb = ((lane >> 3) & 1) * 16;               // B ldmatrix k-byte

    for (int s = 0; s < S; ++s) {
        if (s) __syncthreads();    // previous compute done reading smem

        // ---- convert + store slab s ----
        {
            uint2 h[4], l[4];
#pragma unroll
            for (int q = 0; q < 4; ++q) split4(pa[q], h[q], l[q]);
            *(uint4*)(&sAh[r * SSTR + ch])     = make_uint4(h[0].x, h[0].y, h[1].x, h[1].y);
            *(uint4*)(&sAh[r * SSTR + ch + 8]) = make_uint4(h[2].x, h[2].y, h[3].x, h[3].y);
            *(uint4*)(&sAl[r * SSTR + ch])     = make_uint4(l[0].x, l[0].y, l[1].x, l[1].y);
            *(uint4*)(&sAl[r * SSTR + ch + 8]) = make_uint4(l[2].x, l[2].y, l[3].x, l[3].y);
#pragma unroll
            for (int q = 0; q < 4; ++q) split4(pb[q], h[q], l[q]);
            *(uint4*)(&sBh[r * SSTR + ch])     = make_uint4(h[0].x, h[0].y, h[1].x, h[1].y);
            *(uint4*)(&sBh[r * SSTR + ch + 8]) = make_uint4(h[2].x, h[2].y, h[3].x, h[3].y);
            *(uint4*)(&sBl[r * SSTR + ch])     = make_uint4(l[0].x, l[0].y, l[1].x, l[1].y);
            *(uint4*)(&sBl[r * SSTR + ch + 8]) = make_uint4(l[2].x, l[2].y, l[3].x, l[3].y);
        }
        __syncthreads();

        // ---- prefetch slab s+1 (fp32) ----
        if (s + 1 < S) {
            const float* ap;
            const float* bp;
            if (MODE == 0) {
                const int k0 = (s + 1) * 32;
                ap = arowbase + k0 + ch;
                bp = Bg + (size_t)dir0 * NPROJ * DM + (size_t)nrow * DM + k0 + ch;
            } else {
                const int d  = (s + 1) / (DI / 32);
                const int k0 = ((s + 1) % (DI / 32)) * 32;
                const int m = m0 + r, t = m & (L - 1);
                const int srcm = d ? (m - t + (L - 1 - t)) : m;
                ap = g_y + ((size_t)(d * M4 + srcm)) * DI + k0 + ch;
                bp = Bg + (size_t)d * DM * DI + (size_t)nrow * DI + k0 + ch;
            }
#pragma unroll
            for (int q = 0; q < 4; ++q) pa[q] = *(const float4*)(ap + q * 4);
            if (bvalid) {
#pragma unroll
                for (int q = 0; q < 4; ++q) pb[q] = *(const float4*)(bp + q * 4);
            } else {
#pragma unroll
                for (int q = 0; q < 4; ++q) pb[q] = make_float4(0.f, 0.f, 0.f, 0.f);
            }
        }

        // ---- mma over 2 k-steps, 3 products each ----
#pragma unroll
        for (int ks = 0; ks < 2; ++ks) {
            uint32_t ah[4][4], al_[4][4], bh[2][4], bl[2][4];
#pragma unroll
            for (int mf = 0; mf < 4; ++mf) {
                const uint32_t off = (uint32_t)(wm + mf * 16 + arl) * 80 + ks * 32 + akb;
                ldsm4(ah[mf][0],  ah[mf][1],  ah[mf][2],  ah[mf][3],  uAh + off);
                ldsm4(al_[mf][0], al_[mf][1], al_[mf][2], al_[mf][3], uAl + off);
            }
#pragma unroll
            for (int nf2 = 0; nf2 < 2; ++nf2) {
                const uint32_t off = (uint32_t)(wn + nf2 * 16 + brl) * 80 + ks * 32 + bkb;
                ldsm4(bh[nf2][0], bh[nf2][1], bh[nf2][2], bh[nf2][3], uBh + off);
                ldsm4(bl[nf2][0], bl[nf2][1], bl[nf2][2], bl[nf2][3], uBl + off);
            }
#pragma unroll
            for (int mf = 0; mf < 4; ++mf)
#pragma unroll
                for (int nf = 0; nf < 4; ++nf) {
                    const uint32_t* bhp = &bh[nf >> 1][(nf & 1) * 2];
                    const uint32_t* blp = &bl[nf >> 1][(nf & 1) * 2];
                    mma16816(acc[mf][nf], ah[mf],  bhp);
                    mma16816(acc[mf][nf], ah[mf],  blp);
                    mma16816(acc[mf][nf], al_[mf], bhp);
                }
        }
    }

    // ---- epilogue ----
    const int g  = lane >> 2;
    const int tg = lane & 3;
#pragma unroll
    for (int mf = 0; mf < 4; ++mf)
#pragma unroll
        for (int nf = 0; nf < 4; ++nf) {
            const int mrow = m0 + wm + mf * 16 + g;
            const int ncol = n0 + wn + nf * 8 + tg * 2;
            const float* c = acc[mf][nf];
            if (MODE == 0) {
                if (ncol < NPROJ) {
                    float* o0 = g_zx + ((size_t)(dir0 * M4 + mrow)) * NPROJ + ncol;
                    float* o1 = g_zx + ((size_t)(dir0 * M4 + mrow + 8)) * NPROJ + ncol;
                    o0[0] = c[0]; o0[1] = c[1];
                    o1[0] = c[2]; o1[1] = c[3];
                }
            } else {
                float* o0 = Cg + (size_t)mrow * DM + ncol;
                float* o1 = Cg + (size_t)(mrow + 8) * DM + ncol;
                o0[0] = c[0]; o0[1] = c[1];
                o1[0] = c[2]; o1[1] = c[3];
            }
        }
}

// =====================================================================
// dt/dA precompute
// =====================================================================
__global__ void dtdA_kernel(const float* __restrict__ dt_bias,
                            const float* __restrict__ A_log)
{
    const int idx = blockIdx.x * 256 + threadIdx.x;
    if (idx >= 2 * M4 * NH) return;
    const int hh  = idx % NH;
    const int rm  = idx / NH;
    const int dir = rm >> 12;
    const float raw = g_zx[(size_t)rm * NPROJ + (DI + CONVD) + hh] + dt_bias[dir * NH + hh];
    const float dtv = (raw > 20.f) ? raw : log1pf(expf(raw));
    const float A   = -expf(A_log[dir * NH + hh]);
    g_dt[idx] = dtv;
    g_dA[idx] = expf(dtv * A);
}

// =====================================================================
// depthwise causal conv(4) + SiLU
// =====================================================================
__global__ void __launch_bounds__(256) conv_kernel(const float* __restrict__ conv_w,
                                                   const float* __restrict__ conv_b)
{
    const int db  = blockIdx.z;
    const int dir = db >> 1;
    const int b   = db & 1;
    const int t0  = blockIdx.y * 32;
    const int tid = threadIdx.x;

    __shared__ float s[35][256];

    for (int cbk = 0; cbk < CONVD; cbk += 256) {
        const int c = cbk + tid;
        __syncthreads();
#pragma unroll
        for (int rr = 0; rr < 35; ++rr) {
            const int tin = t0 - 3 + rr;
            float val = 0.f;
            if (tin >= 0)
                val = g_zx[((size_t)(dir * M4 + b * L + tin)) * NPROJ + DI + c];
            s[rr][tid] = val;
        }
        __syncthreads();
        const float w0 = conv_w[(dir * CONVD + c) * 4 + 0];
        const float w1 = conv_w[(dir * CONVD + c) * 4 + 1];
        const float w2 = conv_w[(dir * CONVD + c) * 4 + 2];
        const float w3 = conv_w[(dir * CONVD + c) * 4 + 3];
        const float bias = conv_b[dir * CONVD + c];
#pragma unroll 4
        for (int tt = 0; tt < 32; ++tt) {
            float v = bias;
            v = fmaf(s[tt + 0][tid], w0, v);
            v = fmaf(s[tt + 1][tid], w1, v);
            v = fmaf(s[tt + 2][tid], w2, v);
            v = fmaf(s[tt + 3][tid], w3, v);
            const float o = v / (1.f + expf(-v));
            g_xBC[((size_t)(dir * M4 + b * L + t0 + tt)) * CONVD + c] = o;
        }
    }
}

// =====================================================================
// selective scan (96 blocks, 128 threads, register-resident state)
// =====================================================================
__global__ void __launch_bounds__(128) scan_kernel(const float* __restrict__ Dvec)
{
    const int h   = blockIdx.x;
    const int b   = blockIdx.y;
    const int dir = blockIdx.z;
    const int tid = threadIdx.x;
    const int ni  = tid & 7;
    const int pi  = tid >> 3;

    __shared__ float sx[3][64];
    __shared__ float sB[3][128];
    __shared__ float sC[3][128];
    __shared__ float ss[3][2];

    const float Dval  = Dvec[dir * NH + h];
    const int rowbase = dir * M4 + b * L;

    float hreg[4][16];
#pragma unroll
    for (int pp = 0; pp < 4; ++pp)
#pragma unroll
        for (int nn = 0; nn < 16; ++nn) hreg[pp][nn] = 0.f;

    {
        const float* row = g_xBC + (size_t)rowbase * CONVD;
        if (tid < 64) sx[0][tid] = row[h * HD + tid];
        sB[0][tid] = row[DI + tid];
        sC[0][tid] = row[DI + DS + tid];
        if (tid == 0) {
            ss[0][0] = g_dt[rowbase * NH + h];
            ss[0][1] = g_dA[rowbase * NH + h];
        }
    }
    __syncthreads();

    int cur = 0;
    for (int t = 0; t < L; ++t) {
        float rx = 0.f, rb = 0.f, rc = 0.f, rdt = 0.f, rdA = 0.f;
        if (t + 1 < L) {
            const float* row = g_xBC + (size_t)(rowbase + t + 1) * CONVD;
            if (tid < 64) rx = row[h * HD + tid];
            rb = row[DI + tid];
            rc = row[DI + DS + tid];
            if (tid == 0) {
                rdt = g_dt[(rowbase + t + 1) * NH + h];
                rdA = g_dA[(rowbase + t + 1) * NH + h];
            }
        }

        const float dt = ss[cur][0];
        const float dA = ss[cur][1];
        float xv[4], coef[4], acc[4];
#pragma unroll
        for (int pp = 0; pp < 4; ++pp) {
            xv[pp]   = sx[cur][pi * 4 + pp];
            coef[pp] = dt * xv[pp];
            acc[pp]  = 0.f;
        }
#pragma unroll
        for (int nn = 0; nn < 16; ++nn) {
            const float Bv = sB[cur][ni * 16 + nn];
            const float Cv = sC[cur][ni * 16 + nn];
#pragma unroll
            for (int pp = 0; pp < 4; ++pp) {
                const float hv = fmaf(hreg[pp][nn], dA, coef[pp] * Bv);
                hreg[pp][nn] = hv;
                acc[pp] = fmaf(hv, Cv, acc[pp]);
            }
        }
#pragma unroll
        for (int pp = 0; pp < 4; ++pp) {
            acc[pp] += __shfl_xor_sync(0xffffffffu, acc[pp], 1);
            acc[pp] += __shfl_xor_sync(0xffffffffu, acc[pp], 2);
            acc[pp] += __shfl_xor_sync(0xffffffffu, acc[pp], 4);
        }
        if (ni == 0) {
            float* yp = g_y + (size_t)(rowbase + t) * DI + h * HD + pi * 4;
#pragma unroll
            for (int pp = 0; pp < 4; ++pp)
                yp[pp] = fmaf(Dval, xv[pp], acc[pp]);
        }

        const int nxt = (cur == 2) ? 0 : cur + 1;
        if (t + 1 < L) {
            if (tid < 64) sx[nxt][tid] = rx;
            sB[nxt][tid] = rb;
            sC[nxt][tid] = rc;
            if (tid == 0) { ss[nxt][0] = rdt; ss[nxt][1] = rdA; }
        }
        __syncthreads();
        cur = nxt;
    }
}

// =====================================================================
// gate + RMSNorm (in place on g_y)
// =====================================================================
__global__ void __launch_bounds__(256) gatenorm_kernel(const float* __restrict__ norm_w)
{
    const int row = blockIdx.x;
    const int dir = row >> 12;
    const int tid = threadIdx.x;
    float* yrow = g_y + (size_t)row * DI;
    const float* zrow = g_zx + (size_t)row * NPROJ;

    float v[6];
    float ssum = 0.f;
#pragma unroll
    for (int i = 0; i < 6; ++i) {
        const int c = tid + i * 256;
        const float zv = zrow[c];
        const float val = yrow[c] * (zv / (1.f + expf(-zv)));
        v[i] = val;
        ssum += val * val;
    }
#pragma unroll
    for (int o = 16; o > 0; o >>= 1)
        ssum += __shfl_xor_sync(0xffffffffu, ssum, o);

    __shared__ float red[8];
    if ((tid & 31) == 0) red[tid >> 5] = ssum;
    __syncthreads();
    if (tid == 0) {
        float tot = 0.f;
#pragma unroll
        for (int i = 0; i < 8; ++i) tot += red[i];
        red[0] = rsqrtf(tot / (float)DI + 1e-5f);
    }
    __syncthreads();
    const float scale = red[0];
#pragma unroll
    for (int i = 0; i < 6; ++i) {
        const int c = tid + i * 256;
        yrow[c] = v[i] * scale * norm_w[dir * DI + c];
    }
}

// =====================================================================
// launch
// =====================================================================
extern "C" void kernel_launch(void* const* d_in, const int* in_sizes, int n_in,
                              void* d_out, int out_size)
{
    (void)in_sizes; (void)n_in; (void)out_size;
    const float* x       = (const float*)d_in[0];
    const float* in_w    = (const float*)d_in[1];
    const float* conv_w  = (const float*)d_in[2];
    const float* conv_b  = (const float*)d_in[3];
    const float* dt_bias = (const float*)d_in[4];
    const float* A_log   = (const float*)d_in[5];
    const float* Dp      = (const float*)d_in[6];
    const float* norm_w  = (const float*)d_in[7];
    const float* out_w   = (const float*)d_in[8];
    float* out = (float*)d_out;

    mma_gemm<0><<<dim3((NPROJ + 127) / 128, M4 / 128, 2), 256>>>(x, in_w, nullptr);
    dtdA_kernel<<<(2 * M4 * NH + 255) / 256, 256>>>(dt_bias, A_log);
    conv_kernel<<<dim3(1, L / 32, 4), 256>>>(conv_w, conv_b);
    scan_kernel<<<dim3(NH, BATCH, 2), 128>>>(Dp);
    gatenorm_kernel<<<2 * M4, 256>>>(norm_w);
    mma_gemm<1><<<dim3(DM / 128, M4 / 128, 1), 256>>>(nullptr, out_w, out);
}